// round 1
// baseline (speedup 1.0000x reference)
#include <cuda_runtime.h>
#include <math.h>

#define NW     4096
#define WLEN   16
#define GD     300
#define CE     50
#define CH     128
#define G4     512
#define CV     100
#define HID    512
#define FEAT   428
#define WPB    32
#define LBLOCKS (NW/WPB)   // 128

// ---- device scratch (static, allocation-free) ----
__device__ float g_charGates[CV * G4];   // per-char precomputed input gates (+bias)
__device__ float g_WhhT[CH * G4];        // W_hh transposed to [k][j]
__device__ float g_gsum[GD];             // glove column sums
__device__ float g_hsum[CH];             // char_h column sums

// ---------------------------------------------------------------------------
// Prep: transpose W_hh (512x128 -> 128x512) and zero accumulators.
// grid 128 x 512
// ---------------------------------------------------------------------------
__global__ void prep_transpose_zero(const float* __restrict__ W_hh) {
    int idx = blockIdx.x * 512 + threadIdx.x;   // 0..65535
    int k = idx >> 9;
    int j = idx & 511;
    g_WhhT[idx] = W_hh[j * CH + k];
    if (blockIdx.x == 0) {
        if (threadIdx.x < GD) g_gsum[threadIdx.x] = 0.f;
        if (threadIdx.x < CH) g_hsum[threadIdx.x] = 0.f;
    }
}

// ---------------------------------------------------------------------------
// Prep: charGates[c][j] = b_ih[j] + b_hh[j] + sum_k W_ih[j][k] * char_embed[c][k]
// grid 100 x 512
// ---------------------------------------------------------------------------
__global__ void prep_chargates(const float* __restrict__ W_ih,
                               const float* __restrict__ char_embed,
                               const float* __restrict__ b_ih,
                               const float* __restrict__ b_hh) {
    __shared__ float ce[CE];
    int c = blockIdx.x;
    int j = threadIdx.x;
    if (j < CE) ce[j] = char_embed[c * CE + j];
    __syncthreads();
    float acc = b_ih[j] + b_hh[j];
    const float* w = W_ih + j * CE;
#pragma unroll
    for (int k = 0; k < CE; k++) acc = fmaf(w[k], ce[k], acc);
    g_charGates[c * G4 + j] = acc;
}

// ---------------------------------------------------------------------------
// Glove gathered column-sum. grid 128 x 128 (32 words/block, 3 cols/thread)
// ---------------------------------------------------------------------------
__global__ void glove_sum_kernel(const int* __restrict__ widx,
                                 const float* __restrict__ glove) {
    int tid = threadIdx.x;
    int wb = blockIdx.x * 32;
    __shared__ int rows[32];
    if (tid < 32) rows[tid] = widx[wb + tid];
    __syncthreads();
    float a0 = 0.f, a1 = 0.f, a2 = 0.f;
#pragma unroll 4
    for (int w = 0; w < 32; w++) {
        const float* g = glove + (long long)rows[w] * GD;
        a0 += g[tid];
        a1 += g[tid + 128];
        if (tid < GD - 256) a2 += g[tid + 256];
    }
    atomicAdd(&g_gsum[tid], a0);
    atomicAdd(&g_gsum[tid + 128], a1);
    if (tid < GD - 256) atomicAdd(&g_gsum[tid + 256], a2);
}

// ---------------------------------------------------------------------------
// Char LSTM, 16 steps. grid 128 x 512, 32 words/block.
// Thread (tw = tid>>7 in 0..3, tu = tid&127) owns unit tu of words tw*8..tw*8+7:
// computes all 4 gates for its (word, unit) pairs, so c stays in registers.
// h lives in shared [32][129] (broadcast reads, conflict-free).
// ---------------------------------------------------------------------------
__device__ __forceinline__ float sigf(float x) { return 1.f / (1.f + expf(-x)); }

__global__ void __launch_bounds__(512) lstm_kernel(const int* __restrict__ cidx) {
    __shared__ float h_sh[WPB][CH + 1];
    __shared__ int   ci_sh[WPB][WLEN];
    int tid = threadIdx.x;
    int tu = tid & 127;
    int tw = tid >> 7;
    int wb = blockIdx.x * WPB;

    for (int i = tid; i < WPB * WLEN; i += 512)
        ((int*)ci_sh)[i] = cidx[wb * WLEN + i];
    for (int i = tid; i < WPB * (CH + 1); i += 512)
        ((float*)h_sh)[i] = 0.f;

    float cc[8];
#pragma unroll
    for (int w = 0; w < 8; w++) cc[w] = 0.f;
    __syncthreads();

    for (int t = 0; t < WLEN; t++) {
        float ai[8], af[8], ag[8], ao[8];
#pragma unroll
        for (int w = 0; w < 8; w++) {
            const float* cg = g_charGates + ci_sh[tw * 8 + w][t] * G4 + tu;
            ai[w] = cg[0];
            af[w] = cg[128];
            ag[w] = cg[256];
            ao[w] = cg[384];
        }
        const float* W = g_WhhT + tu;
#pragma unroll 4
        for (int k = 0; k < CH; k++) {
            float w0 = W[k * G4];
            float w1 = W[k * G4 + 128];
            float w2 = W[k * G4 + 256];
            float w3 = W[k * G4 + 384];
#pragma unroll
            for (int w = 0; w < 8; w++) {
                float hv = h_sh[tw * 8 + w][k];
                ai[w] = fmaf(w0, hv, ai[w]);
                af[w] = fmaf(w1, hv, af[w]);
                ag[w] = fmaf(w2, hv, ag[w]);
                ao[w] = fmaf(w3, hv, ao[w]);
            }
        }
        __syncthreads();   // all h reads done before overwrite
#pragma unroll
        for (int w = 0; w < 8; w++) {
            float ig = sigf(ai[w]);
            float fg = sigf(af[w]);
            float gg = tanhf(ag[w]);
            float og = sigf(ao[w]);
            float c2 = fmaf(fg, cc[w], ig * gg);
            cc[w] = c2;
            h_sh[tw * 8 + w][tu] = og * tanhf(c2);
        }
        __syncthreads();   // h visible for next step
    }

    if (tw == 0) {  // threads 0..127 reduce the block's 32 final h vectors
        float s = 0.f;
#pragma unroll
        for (int w = 0; w < WPB; w++) s += h_sh[w][tu];
        atomicAdd(&g_hsum[tu], s);
    }
}

// ---------------------------------------------------------------------------
// Final: avg -> fc1 + relu -> fc2. 1 x 512
// ---------------------------------------------------------------------------
__global__ void final_kernel(const float* __restrict__ fc1_w,
                             const float* __restrict__ fc1_b,
                             const float* __restrict__ fc2_w,
                             const float* __restrict__ fc2_b,
                             float* __restrict__ out) {
    __shared__ float avg[FEAT];
    __shared__ float r0[16], r1[16];
    int tid = threadIdx.x;
    if (tid < GD) avg[tid] = g_gsum[tid] * (1.f / NW);
    else if (tid < FEAT) avg[tid] = g_hsum[tid - GD] * (1.f / NW);
    __syncthreads();

    float h = fc1_b[tid];
    const float* w = fc1_w + tid * FEAT;
#pragma unroll 4
    for (int k = 0; k < FEAT; k++) h = fmaf(w[k], avg[k], h);
    h = fmaxf(h, 0.f);

    float p0 = fc2_w[tid] * h;
    float p1 = fc2_w[HID + tid] * h;
#pragma unroll
    for (int off = 16; off; off >>= 1) {
        p0 += __shfl_down_sync(0xffffffffu, p0, off);
        p1 += __shfl_down_sync(0xffffffffu, p1, off);
    }
    int warp = tid >> 5, lane = tid & 31;
    if (lane == 0) { r0[warp] = p0; r1[warp] = p1; }
    __syncthreads();
    if (tid == 0) {
        float a = 0.f, b = 0.f;
#pragma unroll
        for (int i = 0; i < 16; i++) { a += r0[i]; b += r1[i]; }
        out[0] = a + fc2_b[0];
        out[1] = b + fc2_b[1];
    }
}

// ---------------------------------------------------------------------------
extern "C" void kernel_launch(void* const* d_in, const int* in_sizes, int n_in,
                              void* d_out, int out_size) {
    const int*   widx  = (const int*)d_in[0];
    const int*   cidx  = (const int*)d_in[1];
    const float* glove = (const float*)d_in[2];
    const float* cemb  = (const float*)d_in[3];
    const float* W_ih  = (const float*)d_in[4];
    const float* W_hh  = (const float*)d_in[5];
    const float* b_ih  = (const float*)d_in[6];
    const float* b_hh  = (const float*)d_in[7];
    const float* fc1_w = (const float*)d_in[8];
    const float* fc1_b = (const float*)d_in[9];
    const float* fc2_w = (const float*)d_in[10];
    const float* fc2_b = (const float*)d_in[11];
    float* out = (float*)d_out;

    prep_transpose_zero<<<128, 512>>>(W_hh);
    prep_chargates<<<CV, 512>>>(W_ih, cemb, b_ih, b_hh);
    glove_sum_kernel<<<128, 128>>>(widx, glove);
    lstm_kernel<<<LBLOCKS, 512>>>(cidx);
    final_kernel<<<1, 512>>>(fc1_w, fc1_b, fc2_w, fc2_b, out);
}

// round 2
// speedup vs baseline: 1.0739x; 1.0739x over previous
#include <cuda_runtime.h>
#include <math.h>

#define NW     4096
#define WLEN   16
#define GD     300
#define CE     50
#define CH     128
#define G4     512
#define CV     100
#define HID    512
#define FEAT   428
#define WPB    32
#define LBLOCKS (NW/WPB)   // 128

typedef unsigned long long ull;

// ---- device scratch (static, allocation-free) ----
__device__ float g_cgq[CV * G4];    // charGates permuted: [c][unit*4+gate]
__device__ float g_Wq[CH * G4];     // W_hh permuted:      [k][unit*4+gate]
__device__ float g_gsum[GD];
__device__ float g_hsum[CH];

// ---- f32x2 helpers (sm_103a packed-fp32 pipe) ----
__device__ __forceinline__ ull pk2(float a, float b) {
    ull r; asm("mov.b64 %0, {%1,%2};" : "=l"(r) : "f"(a), "f"(b)); return r;
}
__device__ __forceinline__ void upk2(float& a, float& b, ull v) {
    asm("mov.b64 {%0,%1}, %2;" : "=f"(a), "=f"(b) : "l"(v));
}
__device__ __forceinline__ ull fma2(ull a, ull b, ull c) {
    ull d; asm("fma.rn.f32x2 %0, %1, %2, %3;" : "=l"(d) : "l"(a), "l"(b), "l"(c)); return d;
}

// fast, accurate-enough activations (abs err ~1e-7)
__device__ __forceinline__ float sigf(float x) {
    float e = __expf(-x);
    return __fdividef(1.f, 1.f + e);
}
__device__ __forceinline__ float tanhp(float x) {
    return fmaf(2.f, sigf(2.f * x), -1.f);
}

// ---------------------------------------------------------------------------
// Prep: Wq[k][u*4+g] = W_hh[g*128+u][k]; zero accumulators. grid 128 x 512
// ---------------------------------------------------------------------------
__global__ void prep_wq(const float* __restrict__ W_hh) {
    int k = blockIdx.x;
    int n = threadIdx.x;             // unit*4 + gate
    int g = n & 3, u = n >> 2;
    g_Wq[k * G4 + n] = W_hh[(g * CH + u) * CH + k];
    if (k == 0) {
        if (n < GD) g_gsum[n] = 0.f;
        if (n < CH) g_hsum[n] = 0.f;
    }
}

// ---------------------------------------------------------------------------
// Prep: cgq[c][u*4+g] = b_ih[r]+b_hh[r] + sum_e W_ih[r][e]*cemb[c][e], r=g*128+u
// grid 100 x 512
// ---------------------------------------------------------------------------
__global__ void prep_cgq(const float* __restrict__ W_ih,
                         const float* __restrict__ char_embed,
                         const float* __restrict__ b_ih,
                         const float* __restrict__ b_hh) {
    __shared__ float ce[CE];
    int c = blockIdx.x;
    int n = threadIdx.x;
    if (n < CE) ce[n] = char_embed[c * CE + n];
    __syncthreads();
    int g = n & 3, u = n >> 2;
    int r = g * CH + u;
    float acc = b_ih[r] + b_hh[r];
    const float* w = W_ih + r * CE;
#pragma unroll
    for (int e = 0; e < CE; e++) acc = fmaf(w[e], ce[e], acc);
    g_cgq[c * G4 + n] = acc;
}

// ---------------------------------------------------------------------------
// Glove gathered column-sum. grid 128 x 128
// ---------------------------------------------------------------------------
__global__ void glove_sum_kernel(const int* __restrict__ widx,
                                 const float* __restrict__ glove) {
    int tid = threadIdx.x;
    int wb = blockIdx.x * 32;
    __shared__ int rows[32];
    if (tid < 32) rows[tid] = widx[wb + tid];
    __syncthreads();
    float a0 = 0.f, a1 = 0.f, a2 = 0.f;
#pragma unroll 8
    for (int w = 0; w < 32; w++) {
        const float* g = glove + (long long)rows[w] * GD;
        a0 += g[tid];
        a1 += g[tid + 128];
        if (tid < GD - 256) a2 += g[tid + 256];
    }
    atomicAdd(&g_gsum[tid], a0);
    atomicAdd(&g_gsum[tid + 128], a1);
    if (tid < GD - 256) atomicAdd(&g_gsum[tid + 256], a2);
}

// ---------------------------------------------------------------------------
// Char LSTM via packed f32x2. grid 128 x 512, 32 words/block.
// Thread (tw=tid>>7 in 0..3, tu=tid&127) owns unit tu of words tw*8..tw*8+7,
// held as 4 f32x2 word-pairs per gate. h lives in smem as u64 pairs
// [unit][pair] (broadcast LDS.64 in the mainloop).
// ---------------------------------------------------------------------------
__global__ void __launch_bounds__(512) lstm_kernel(const int* __restrict__ cidx) {
    __shared__ ull  h_sh[CH][WPB / 2 + 1];   // [unit][word-pair], stride 17 (8B elems)
    __shared__ int  ci_sh[WPB][WLEN];
    int tid = threadIdx.x;
    int tu = tid & 127;
    int tw = tid >> 7;
    int tw4 = tw * 4;
    int wb = blockIdx.x * WPB;

    for (int i = tid; i < WPB * WLEN; i += 512)
        ((int*)ci_sh)[i] = cidx[wb * WLEN + i];
    for (int i = tid; i < CH * (WPB / 2 + 1); i += 512)
        ((ull*)h_sh)[i] = 0ull;

    float cc[8];
#pragma unroll
    for (int w = 0; w < 8; w++) cc[w] = 0.f;
    __syncthreads();

    const float4* Wq4 = (const float4*)g_Wq;   // [k][u] -> 4 gate weights
    const float4* cg4 = (const float4*)g_cgq;  // [c][u] -> 4 gate inputs

    for (int t = 0; t < WLEN; t++) {
        // init accumulators from per-char precomputed gates (word-pairs packed)
        ull ai[4], af[4], ag[4], ao[4];
#pragma unroll
        for (int j = 0; j < 4; j++) {
            int cA = ci_sh[tw * 8 + 2 * j][t];
            int cB = ci_sh[tw * 8 + 2 * j + 1][t];
            float4 a = cg4[cA * (G4 / 4) + tu];
            float4 b = cg4[cB * (G4 / 4) + tu];
            ai[j] = pk2(a.x, b.x);
            af[j] = pk2(a.y, b.y);
            ag[j] = pk2(a.z, b.z);
            ao[j] = pk2(a.w, b.w);
        }

        // recurrent GEMM: 1 LDG.128 + 4 LDS.64 + 16 FFMA2 per k
#pragma unroll 4
        for (int k = 0; k < CH; k++) {
            float4 w = Wq4[k * (G4 / 4) + tu];
            ull wi = pk2(w.x, w.x);
            ull wf = pk2(w.y, w.y);
            ull wg = pk2(w.z, w.z);
            ull wo = pk2(w.w, w.w);
#pragma unroll
            for (int j = 0; j < 4; j++) {
                ull h2 = h_sh[k][tw4 + j];
                ai[j] = fma2(wi, h2, ai[j]);
                af[j] = fma2(wf, h2, af[j]);
                ag[j] = fma2(wg, h2, ag[j]);
                ao[j] = fma2(wo, h2, ao[j]);
            }
        }
        __syncthreads();   // all h reads done before overwrite

        // pointwise LSTM cell, write next h as packed pairs
#pragma unroll
        for (int j = 0; j < 4; j++) {
            float i0, i1, f0, f1, g0, g1, o0, o1;
            upk2(i0, i1, ai[j]);
            upk2(f0, f1, af[j]);
            upk2(g0, g1, ag[j]);
            upk2(o0, o1, ao[j]);
            float c0 = fmaf(sigf(f0), cc[2 * j],     sigf(i0) * tanhp(g0));
            float c1 = fmaf(sigf(f1), cc[2 * j + 1], sigf(i1) * tanhp(g1));
            cc[2 * j] = c0;
            cc[2 * j + 1] = c1;
            float h0 = sigf(o0) * tanhp(c0);
            float h1 = sigf(o1) * tanhp(c1);
            h_sh[tu][tw4 + j] = pk2(h0, h1);
        }
        __syncthreads();   // h visible for next step
    }

    if (tw == 0) {   // threads 0..127 reduce the block's 32 final h vectors
        float s = 0.f;
#pragma unroll
        for (int p = 0; p < WPB / 2; p++) {
            float a, b;
            upk2(a, b, h_sh[tu][p]);
            s += a + b;
        }
        atomicAdd(&g_hsum[tu], s);
    }
}

// ---------------------------------------------------------------------------
// Final: avg -> fc1 + relu -> fc2. 1 x 512
// ---------------------------------------------------------------------------
__global__ void final_kernel(const float* __restrict__ fc1_w,
                             const float* __restrict__ fc1_b,
                             const float* __restrict__ fc2_w,
                             const float* __restrict__ fc2_b,
                             float* __restrict__ out) {
    __shared__ float avg[FEAT];
    __shared__ float r0[16], r1[16];
    int tid = threadIdx.x;
    if (tid < GD) avg[tid] = g_gsum[tid] * (1.f / NW);
    else if (tid < FEAT) avg[tid] = g_hsum[tid - GD] * (1.f / NW);
    __syncthreads();

    float h = fc1_b[tid];
    const float* w = fc1_w + tid * FEAT;
#pragma unroll 4
    for (int k = 0; k < FEAT; k++) h = fmaf(w[k], avg[k], h);
    h = fmaxf(h, 0.f);

    float p0 = fc2_w[tid] * h;
    float p1 = fc2_w[HID + tid] * h;
#pragma unroll
    for (int off = 16; off; off >>= 1) {
        p0 += __shfl_down_sync(0xffffffffu, p0, off);
        p1 += __shfl_down_sync(0xffffffffu, p1, off);
    }
    int warp = tid >> 5, lane = tid & 31;
    if (lane == 0) { r0[warp] = p0; r1[warp] = p1; }
    __syncthreads();
    if (tid == 0) {
        float a = 0.f, b = 0.f;
#pragma unroll
        for (int i = 0; i < 16; i++) { a += r0[i]; b += r1[i]; }
        out[0] = a + fc2_b[0];
        out[1] = b + fc2_b[1];
    }
}

// ---------------------------------------------------------------------------
extern "C" void kernel_launch(void* const* d_in, const int* in_sizes, int n_in,
                              void* d_out, int out_size) {
    const int*   widx  = (const int*)d_in[0];
    const int*   cidx  = (const int*)d_in[1];
    const float* glove = (const float*)d_in[2];
    const float* cemb  = (const float*)d_in[3];
    const float* W_ih  = (const float*)d_in[4];
    const float* W_hh  = (const float*)d_in[5];
    const float* b_ih  = (const float*)d_in[6];
    const float* b_hh  = (const float*)d_in[7];
    const float* fc1_w = (const float*)d_in[8];
    const float* fc1_b = (const float*)d_in[9];
    const float* fc2_w = (const float*)d_in[10];
    const float* fc2_b = (const float*)d_in[11];
    float* out = (float*)d_out;

    prep_wq<<<128, 512>>>(W_hh);
    prep_cgq<<<CV, 512>>>(W_ih, cemb, b_ih, b_hh);
    glove_sum_kernel<<<128, 128>>>(widx, glove);
    lstm_kernel<<<LBLOCKS, 512>>>(cidx);
    final_kernel<<<1, 512>>>(fc1_w, fc1_b, fc2_w, fc2_b, out);
}

// round 4
// speedup vs baseline: 3.5447x; 3.3007x over previous
#include <cuda_runtime.h>
#include <cuda_fp16.h>
#include <math.h>
#include <stdint.h>

#define NW     4096
#define WLEN   16
#define GD     300
#define CE     50
#define CH     128
#define G4     512
#define CV     100
#define HID    512
#define FEAT   428

#define MW     32                 // words per CTA (MMA M)
#define THR    512                // 16 warps, each owns 32 gate columns
#define NBLK   (NW / MW)          // 128
#define KEXT   192                // 128 h + 50 emb + 1 bias + 13 pad
#define KATOMS (KEXT / 16)        // 12
#define ROWB   400                // smem row stride bytes (200 halves) - conflict-free

// ---- smem layout ----
#define SM_CI   0                          // 32*16*4 = 2048
#define SM_A    2048                       // 32*400 = 12800
#define SM_B    (2048 + MW * ROWB)         // 14848; 512*400 = 204800
#define SM_TOTAL (SM_B + G4 * ROWB)        // 219648

// ---- device scratch ----
__device__ __align__(16) __half g_Bext[G4 * KEXT];  // permuted fused weights
__device__ __align__(16) __half g_embq[CV * 64];    // [emb(50) | 1 | 0pad] per char
__device__ float g_gsum[GD];
__device__ float g_hsum[CH];

// ---- helpers ----
__device__ __forceinline__ uint32_t smem_u32(const void* p) {
    uint32_t a;
    asm("{ .reg .u64 t; cvta.to.shared.u64 t, %1; cvt.u32.u64 %0, t; }" : "=r"(a) : "l"(p));
    return a;
}
__device__ __forceinline__ void ldsm4(uint32_t addr, uint32_t r[4]) {
    asm volatile("ldmatrix.sync.aligned.m8n8.x4.shared.b16 {%0,%1,%2,%3}, [%4];"
        : "=r"(r[0]), "=r"(r[1]), "=r"(r[2]), "=r"(r[3]) : "r"(addr));
}
__device__ __forceinline__ void mma16816(float d[4], const uint32_t a[4], const uint32_t b[2]) {
    asm volatile("mma.sync.aligned.m16n8k16.row.col.f32.f16.f16.f32 "
        "{%0,%1,%2,%3}, {%4,%5,%6,%7}, {%8,%9}, {%0,%1,%2,%3};"
        : "+f"(d[0]), "+f"(d[1]), "+f"(d[2]), "+f"(d[3])
        : "r"(a[0]), "r"(a[1]), "r"(a[2]), "r"(a[3]), "r"(b[0]), "r"(b[1]));
}
// proven-accurate activations (round-2: total rel_err 6e-5)
__device__ __forceinline__ float sigf(float x) {
    return __fdividef(1.f, 1.f + __expf(-x));
}
__device__ __forceinline__ float tanhp(float x) {
    return fmaf(2.f, sigf(2.f * x), -1.f);
}

// gate-column permutation: warp w owns cols j = w*32 + c, c = a*8 + q*2 + e
//   gate g = 2*(a>>1) + e   (atoms 0,1 -> i,f ; atoms 2,3 -> g,o)
//   unit u = w*8 + (a&1)*4 + q

// ---------------------------------------------------------------------------
// Prep: fused B_ext[j][k] fp16, permuted columns. grid 512 x 96
// ---------------------------------------------------------------------------
__global__ void prep_b(const float* __restrict__ W_hh, const float* __restrict__ W_ih,
                       const float* __restrict__ b_ih, const float* __restrict__ b_hh) {
    int j = blockIdx.x;
    int w = j >> 5, c = j & 31;
    int a = c >> 3, q = (c >> 1) & 3, e = c & 1;
    int g = 2 * (a >> 1) + e;
    int u = w * 8 + (a & 1) * 4 + q;
    int row = g * CH + u;
    int k0 = threadIdx.x * 2;
    float v[2];
#pragma unroll
    for (int d = 0; d < 2; d++) {
        int k = k0 + d;
        float x;
        if (k < CH)            x = W_hh[row * CH + k];
        else if (k < CH + CE)  x = W_ih[row * CE + (k - CH)];
        else if (k == CH + CE) x = b_ih[row] + b_hh[row];
        else                   x = 0.f;
        v[d] = x;
    }
    *(__half2*)(g_Bext + j * KEXT + k0) = __floats2half2_rn(v[0], v[1]);
}

// ---------------------------------------------------------------------------
// Prep: char emb rows fp16 ([emb | 1 | 0]); zero accumulators. grid 100 x 64
// ---------------------------------------------------------------------------
__global__ void prep_embq(const float* __restrict__ char_embed) {
    int cix = blockIdx.x, k = threadIdx.x;
    float v = (k < CE) ? char_embed[cix * CE + k] : (k == CE ? 1.f : 0.f);
    g_embq[cix * 64 + k] = __float2half(v);
    int z = blockIdx.x * 64 + threadIdx.x;
    if (z < GD) g_gsum[z] = 0.f;
    if (z < CH) g_hsum[z] = 0.f;
}

// ---------------------------------------------------------------------------
// Glove gathered column-sum. grid 256 x 128 (16 words/block)
// ---------------------------------------------------------------------------
__global__ void glove_sum_kernel(const int* __restrict__ widx,
                                 const float* __restrict__ glove) {
    int tid = threadIdx.x;
    int wb = blockIdx.x * 16;
    __shared__ int rows[16];
    if (tid < 16) rows[tid] = widx[wb + tid];
    __syncthreads();
    float a0 = 0.f, a1 = 0.f, a2 = 0.f;
#pragma unroll
    for (int w = 0; w < 16; w++) {
        const float* g = glove + (long long)rows[w] * GD;
        a0 += g[tid];
        a1 += g[tid + 128];
        if (tid < GD - 256) a2 += g[tid + 256];
    }
    atomicAdd(&g_gsum[tid], a0);
    atomicAdd(&g_gsum[tid + 128], a1);
    if (tid < GD - 256) atomicAdd(&g_gsum[tid + 256], a2);
}

// ---------------------------------------------------------------------------
// LSTM via mma.sync: 128 CTAs x 512 thr; M=32 words, N=512 gates, K=192.
// B_ext resident in smem; A = [h | emb | 1] rewritten per step; c in regs.
// ---------------------------------------------------------------------------
__global__ void __launch_bounds__(THR, 1) lstm_mma_kernel(const int* __restrict__ cidx) {
    extern __shared__ unsigned char sm[];
    uint32_t smb = smem_u32(sm);
    int tid = threadIdx.x;
    int w = tid >> 5, lane = tid & 31;
    int q = lane & 3, r = lane >> 2;

    const int wb = blockIdx.x * MW;
    for (int i = tid; i < MW * WLEN; i += THR)
        ((int*)(sm + SM_CI))[i] = cidx[wb * WLEN + i];
    for (int i = tid; i < MW * ROWB / 16; i += THR)
        ((uint4*)(sm + SM_A))[i] = make_uint4(0, 0, 0, 0);
    for (int i = tid; i < G4 * 24; i += THR) {        // 24 uint4 per 192-half row
        int row = i / 24, s = i % 24;
        *(uint4*)(sm + SM_B + row * ROWB + s * 16) =
            *(const uint4*)((const unsigned char*)g_Bext + i * 16);
    }
    __syncthreads();

    // ldmatrix base addresses
    uint32_t aBase = smb + SM_A + (lane & 15) * ROWB + (lane >> 4) * 16;
    uint32_t bBase = smb + SM_B + (w * 32 + (lane >> 4) * 8 + (lane & 7)) * ROWB
                   + ((lane >> 3) & 1) * 16;

    float cst[8];
#pragma unroll
    for (int i = 0; i < 8; i++) cst[i] = 0.f;

#pragma unroll 1
    for (int t = 0; t < WLEN; t++) {
        // stage char-emb ext block for this step (1 uint4 per thread for tid<256)
        if (tid < 256) {
            int word = tid >> 3, seg = tid & 7;
            int ch = ((const int*)(sm + SM_CI))[word * WLEN + t];
            *(uint4*)(sm + SM_A + word * ROWB + 256 + seg * 16) =
                *(const uint4*)((const unsigned char*)g_embq + ch * 128 + seg * 16);
        }
        __syncthreads();   // A (h from prev epilogue + ext) visible to all

        float acc[2][4][4];
#pragma unroll
        for (int m2 = 0; m2 < 2; m2++)
#pragma unroll
            for (int n = 0; n < 4; n++)
#pragma unroll
                for (int x = 0; x < 4; x++) acc[m2][n][x] = 0.f;

#pragma unroll
        for (int ka = 0; ka < KATOMS; ka++) {
            uint32_t af[2][4], bf[2][4];
            ldsm4(aBase + ka * 32, af[0]);
            ldsm4(aBase + 16 * ROWB + ka * 32, af[1]);
            ldsm4(bBase + ka * 32, bf[0]);
            ldsm4(bBase + 16 * ROWB + ka * 32, bf[1]);
#pragma unroll
            for (int m2 = 0; m2 < 2; m2++)
#pragma unroll
                for (int n = 0; n < 4; n++)
                    mma16816(acc[m2][n], af[m2], &bf[n >> 1][(n & 1) * 2]);
        }
        __syncthreads();   // all A reads done before h overwrite

        float hs0 = 0.f, hs1 = 0.f;
#pragma unroll
        for (int m2 = 0; m2 < 2; m2++)
#pragma unroll
            for (int h2 = 0; h2 < 2; h2++)
#pragma unroll
                for (int al = 0; al < 2; al++) {
                    float iv = acc[m2][al][h2 * 2];
                    float fv = acc[m2][al][h2 * 2 + 1];
                    float gv = acc[m2][al + 2][h2 * 2];
                    float ov = acc[m2][al + 2][h2 * 2 + 1];
                    int ci = (m2 * 2 + h2) * 2 + al;
                    float cn = fmaf(sigf(fv), cst[ci], sigf(iv) * tanhp(gv));
                    cst[ci] = cn;
                    float hv = sigf(ov) * tanhp(cn);
                    int m = m2 * 16 + r + h2 * 8;
                    int u = w * 8 + al * 4 + q;
                    *(__half*)(sm + SM_A + m * ROWB + u * 2) = __float2half(hv);
                    if (al == 0) hs0 += hv; else hs1 += hv;
                }

        if (t == WLEN - 1) {
#pragma unroll
            for (int off = 4; off < 32; off <<= 1) {
                hs0 += __shfl_xor_sync(0xffffffffu, hs0, off);
                hs1 += __shfl_xor_sync(0xffffffffu, hs1, off);
            }
            if (lane < 4) {
                atomicAdd(&g_hsum[w * 8 + lane], hs0);
                atomicAdd(&g_hsum[w * 8 + 4 + lane], hs1);
            }
        }
    }
}

// ---------------------------------------------------------------------------
// Final: avg -> fc1 + relu -> fc2. 1 x 512
// ---------------------------------------------------------------------------
__global__ void final_kernel(const float* __restrict__ fc1_w,
                             const float* __restrict__ fc1_b,
                             const float* __restrict__ fc2_w,
                             const float* __restrict__ fc2_b,
                             float* __restrict__ out) {
    __shared__ float avg[FEAT];
    __shared__ float r0[16], r1[16];
    int tid = threadIdx.x;
    if (tid < GD) avg[tid] = g_gsum[tid] * (1.f / NW);
    else if (tid < FEAT) avg[tid] = g_hsum[tid - GD] * (1.f / NW);
    __syncthreads();

    float h = fc1_b[tid];
    const float* w = fc1_w + tid * FEAT;
#pragma unroll 4
    for (int k = 0; k < FEAT; k++) h = fmaf(w[k], avg[k], h);
    h = fmaxf(h, 0.f);

    float p0 = fc2_w[tid] * h;
    float p1 = fc2_w[HID + tid] * h;
#pragma unroll
    for (int off = 16; off; off >>= 1) {
        p0 += __shfl_down_sync(0xffffffffu, p0, off);
        p1 += __shfl_down_sync(0xffffffffu, p1, off);
    }
    int warp = tid >> 5, lane = tid & 31;
    if (lane == 0) { r0[warp] = p0; r1[warp] = p1; }
    __syncthreads();
    if (tid == 0) {
        float a = 0.f, b = 0.f;
#pragma unroll
        for (int i = 0; i < 16; i++) { a += r0[i]; b += r1[i]; }
        out[0] = a + fc2_b[0];
        out[1] = b + fc2_b[1];
    }
}

// ---------------------------------------------------------------------------
extern "C" void kernel_launch(void* const* d_in, const int* in_sizes, int n_in,
                              void* d_out, int out_size) {
    const int*   widx  = (const int*)d_in[0];
    const int*   cidx  = (const int*)d_in[1];
    const float* glove = (const float*)d_in[2];
    const float* cemb  = (const float*)d_in[3];
    const float* W_ih  = (const float*)d_in[4];
    const float* W_hh  = (const float*)d_in[5];
    const float* b_ih  = (const float*)d_in[6];
    const float* b_hh  = (const float*)d_in[7];
    const float* fc1_w = (const float*)d_in[8];
    const float* fc1_b = (const float*)d_in[9];
    const float* fc2_w = (const float*)d_in[10];
    const float* fc2_b = (const float*)d_in[11];
    float* out = (float*)d_out;

    static int smem_set = 0;
    if (!smem_set) {
        cudaFuncSetAttribute(lstm_mma_kernel,
                             cudaFuncAttributeMaxDynamicSharedMemorySize, SM_TOTAL);
        smem_set = 1;
    }

    prep_b<<<G4, 96>>>(W_hh, W_ih, b_ih, b_hh);
    prep_embq<<<CV, 64>>>(cemb);
    glove_sum_kernel<<<256, 128>>>(widx, glove);
    lstm_mma_kernel<<<NBLK, THR, SM_TOTAL>>>(cidx);
    final_kernel<<<1, 512>>>(fc1_w, fc1_b, fc2_w, fc2_b, out);
}

// round 5
// speedup vs baseline: 3.6820x; 1.0388x over previous
#include <cuda_runtime.h>
#include <cuda_fp16.h>
#include <math.h>
#include <stdint.h>

#define NW     4096
#define WLEN   16
#define GD     300
#define CE     50
#define CH     128
#define G4     512
#define CV     100
#define HID    512
#define FEAT   428

#define MW     32                 // words per CTA (MMA M)
#define THR    512                // 16 warps, each owns 32 gate columns
#define NBLK   (NW / MW)          // 128
#define KEXT   192                // 128 h + 50 emb + 1 bias + 13 pad
#define KATOMS (KEXT / 16)        // 12
#define ROWB   400                // smem row stride bytes (200 halves)

// ---- smem layout ----
#define SM_CI    0                          // 32*16*4 = 2048
#define SM_WIDX  2048                       // 32*4 = 128
#define SM_A     2176                       // 32*400 = 12800
#define SM_B     (SM_A + MW * ROWB)         // 14976; 512*400 = 204800
#define SM_TOTAL (SM_B + G4 * ROWB)         // 219776

// ---- device scratch ----
__device__ __align__(16) __half g_Bext[G4 * KEXT];  // permuted fused weights
__device__ __align__(16) __half g_embq[CV * 64];    // [emb(50) | 1 | 0pad] per char
__device__ float g_gsum[GD];
__device__ float g_hsum[CH];

// ---- helpers ----
__device__ __forceinline__ uint32_t smem_u32(const void* p) {
    uint32_t a;
    asm("{ .reg .u64 t; cvta.to.shared.u64 t, %1; cvt.u32.u64 %0, t; }" : "=r"(a) : "l"(p));
    return a;
}
__device__ __forceinline__ void ldsm4(uint32_t addr, uint32_t r[4]) {
    asm volatile("ldmatrix.sync.aligned.m8n8.x4.shared.b16 {%0,%1,%2,%3}, [%4];"
        : "=r"(r[0]), "=r"(r[1]), "=r"(r[2]), "=r"(r[3]) : "r"(addr));
}
__device__ __forceinline__ void mma16816(float d[4], const uint32_t a[4], const uint32_t b[2]) {
    asm volatile("mma.sync.aligned.m16n8k16.row.col.f32.f16.f16.f32 "
        "{%0,%1,%2,%3}, {%4,%5,%6,%7}, {%8,%9}, {%0,%1,%2,%3};"
        : "+f"(d[0]), "+f"(d[1]), "+f"(d[2]), "+f"(d[3])
        : "r"(a[0]), "r"(a[1]), "r"(a[2]), "r"(a[3]), "r"(b[0]), "r"(b[1]));
}
__device__ __forceinline__ float ex2a(float x) {
    float y; asm("ex2.approx.f32 %0, %1;" : "=f"(y) : "f"(x)); return y;
}
__device__ __forceinline__ float rcpa(float x) {
    float y; asm("rcp.approx.f32 %0, %1;" : "=f"(y) : "f"(x)); return y;
}
#define NL2E (-1.4426950408889634f)

// gate-column permutation: warp w owns cols j = w*32 + c, c = a*8 + q*2 + e
//   gate g = 2*(a>>1) + e ; unit u = w*8 + (a&1)*4 + q

// ---------------------------------------------------------------------------
// Prep (fused): blocks 0..511 build B_ext; blocks 512..611 embq + zero accum.
// grid 612 x 96
// ---------------------------------------------------------------------------
__global__ void prep_all(const float* __restrict__ W_hh, const float* __restrict__ W_ih,
                         const float* __restrict__ b_ih, const float* __restrict__ b_hh,
                         const float* __restrict__ char_embed) {
    if (blockIdx.x < G4) {
        int j = blockIdx.x;
        int w = j >> 5, c = j & 31;
        int a = c >> 3, q = (c >> 1) & 3, e = c & 1;
        int g = 2 * (a >> 1) + e;
        int u = w * 8 + (a & 1) * 4 + q;
        int row = g * CH + u;
        int k0 = threadIdx.x * 2;
        float v[2];
#pragma unroll
        for (int d = 0; d < 2; d++) {
            int k = k0 + d;
            float x;
            if (k < CH)            x = W_hh[row * CH + k];
            else if (k < CH + CE)  x = W_ih[row * CE + (k - CH)];
            else if (k == CH + CE) x = b_ih[row] + b_hh[row];
            else                   x = 0.f;
            v[d] = x;
        }
        *(__half2*)(g_Bext + j * KEXT + k0) = __floats2half2_rn(v[0], v[1]);
    } else {
        int cix = blockIdx.x - G4;
        int k = threadIdx.x;
        if (k < 64) {
            float v = (k < CE) ? char_embed[cix * CE + k] : (k == CE ? 1.f : 0.f);
            g_embq[cix * 64 + k] = __float2half(v);
        }
        int z = cix * 96 + threadIdx.x;
        if (z < GD) g_gsum[z] = 0.f;
        if (z < CH) g_hsum[z] = 0.f;
    }
}

// ---------------------------------------------------------------------------
// LSTM via mma.sync + fused glove gather.
// 128 CTAs x 512 thr; M=32 words, N=512 gates, K=192. B_ext smem-resident.
// ---------------------------------------------------------------------------
__global__ void __launch_bounds__(THR, 1) lstm_mma_kernel(const int* __restrict__ cidx,
                                                          const int* __restrict__ widx,
                                                          const float* __restrict__ glove) {
    extern __shared__ unsigned char sm[];
    uint32_t smb = smem_u32(sm);
    int tid = threadIdx.x;
    int w = tid >> 5, lane = tid & 31;
    int q = lane & 3, r = lane >> 2;

    const int wb = blockIdx.x * MW;
    for (int i = tid; i < MW * WLEN; i += THR)
        ((int*)(sm + SM_CI))[i] = cidx[wb * WLEN + i];
    if (tid < MW) ((int*)(sm + SM_WIDX))[tid] = widx[wb + tid];
    for (int i = tid; i < MW * ROWB / 16; i += THR)
        ((uint4*)(sm + SM_A))[i] = make_uint4(0, 0, 0, 0);
    for (int i = tid; i < G4 * 24; i += THR) {        // 24 uint4 per 192-half row
        int row = i / 24, s = i % 24;
        *(uint4*)(sm + SM_B + row * ROWB + s * 16) =
            *(const uint4*)((const unsigned char*)g_Bext + i * 16);
    }
    __syncthreads();

    // stage emb for t=0
    if (tid < 256) {
        int word = tid >> 3, seg = tid & 7;
        int ch = ((const int*)(sm + SM_CI))[word * WLEN];
        *(uint4*)(sm + SM_A + word * ROWB + 256 + seg * 16) =
            *(const uint4*)((const unsigned char*)g_embq + ch * 128 + seg * 16);
    }
    // fused glove column-sum for this CTA's 32 words (DRAM idle otherwise)
    if (tid < GD) {
        const int* rows = (const int*)(sm + SM_WIDX);
        float s = 0.f;
#pragma unroll
        for (int ww = 0; ww < MW; ww++)
            s += glove[(long long)rows[ww] * GD + tid];
        atomicAdd(&g_gsum[tid], s);
    }
    __syncthreads();

    // ldmatrix base addresses
    uint32_t aBase = smb + SM_A + (lane & 15) * ROWB + (lane >> 4) * 16;
    uint32_t bBase = smb + SM_B + (w * 32 + (lane >> 4) * 8 + (lane & 7)) * ROWB
                   + ((lane >> 3) & 1) * 16;

    float cst[8], hs0 = 0.f, hs1 = 0.f;
#pragma unroll
    for (int i = 0; i < 8; i++) cst[i] = 0.f;

#pragma unroll 1
    for (int t = 0; t < WLEN; t++) {
        float acc[2][4][4];
#pragma unroll
        for (int m2 = 0; m2 < 2; m2++)
#pragma unroll
            for (int n = 0; n < 4; n++)
#pragma unroll
                for (int x = 0; x < 4; x++) acc[m2][n][x] = 0.f;

#pragma unroll
        for (int ka = 0; ka < KATOMS; ka++) {
            uint32_t af[2][4], bf[2][4];
            ldsm4(aBase + ka * 32, af[0]);
            ldsm4(aBase + 16 * ROWB + ka * 32, af[1]);
            ldsm4(bBase + ka * 32, bf[0]);
            ldsm4(bBase + 16 * ROWB + ka * 32, bf[1]);
#pragma unroll
            for (int m2 = 0; m2 < 2; m2++)
#pragma unroll
                for (int n = 0; n < 4; n++)
                    mma16816(acc[m2][n], af[m2], &bf[n >> 1][(n & 1) * 2]);
        }

        // epilogue COMPUTE (registers only) — overlaps MMA across warps,
        // no barrier needed until the h stores below.
        float hreg[8];
#pragma unroll
        for (int m2 = 0; m2 < 2; m2++)
#pragma unroll
            for (int h2 = 0; h2 < 2; h2++)
#pragma unroll
                for (int al = 0; al < 2; al++) {
                    float iv = acc[m2][al][h2 * 2];
                    float fv = acc[m2][al][h2 * 2 + 1];
                    float gv = acc[m2][al + 2][h2 * 2];
                    float ov = acc[m2][al + 2][h2 * 2 + 1];
                    int ci = (m2 * 2 + h2) * 2 + al;
                    // shared-reciprocal gate algebra: 5 ex2 + 3 rcp per unit
                    float ei = ex2a(NL2E * iv);
                    float ef = ex2a(NL2E * fv);
                    float eg = ex2a(2.f * NL2E * gv);
                    float eo = ex2a(NL2E * ov);
                    float fg = rcpa(1.f + ef);
                    float ig = (1.f - eg) * rcpa((1.f + ei) * (1.f + eg));
                    float cn = fmaf(fg, cst[ci], ig);
                    cst[ci] = cn;
                    float ec = ex2a(2.f * NL2E * cn);
                    hreg[ci] = (1.f - ec) * rcpa((1.f + eo) * (1.f + ec));
                }
        __syncthreads();   // all ldsm A-reads done before h/emb overwrite

#pragma unroll
        for (int m2 = 0; m2 < 2; m2++)
#pragma unroll
            for (int h2 = 0; h2 < 2; h2++)
#pragma unroll
                for (int al = 0; al < 2; al++) {
                    int ci = (m2 * 2 + h2) * 2 + al;
                    int m = m2 * 16 + r + h2 * 8;
                    int u = w * 8 + al * 4 + q;
                    *(__half*)(sm + SM_A + m * ROWB + u * 2) = __float2half(hreg[ci]);
                }
        if (t == WLEN - 1) {
#pragma unroll
            for (int ci = 0; ci < 8; ci++) {
                if ((ci & 1) == 0) hs0 += hreg[ci]; else hs1 += hreg[ci];
            }
        } else if (tid < 256) {   // stage emb for t+1
            int word = tid >> 3, seg = tid & 7;
            int ch = ((const int*)(sm + SM_CI))[word * WLEN + t + 1];
            *(uint4*)(sm + SM_A + word * ROWB + 256 + seg * 16) =
                *(const uint4*)((const unsigned char*)g_embq + ch * 128 + seg * 16);
        }
        __syncthreads();   // h + emb visible for next step
    }

    // reduce final h over the CTA's 32 words -> g_hsum
#pragma unroll
    for (int off = 4; off < 32; off <<= 1) {
        hs0 += __shfl_xor_sync(0xffffffffu, hs0, off);
        hs1 += __shfl_xor_sync(0xffffffffu, hs1, off);
    }
    if (lane < 4) {
        atomicAdd(&g_hsum[w * 8 + lane], hs0);
        atomicAdd(&g_hsum[w * 8 + 4 + lane], hs1);
    }
}

// ---------------------------------------------------------------------------
// Final: avg -> fc1 + relu -> fc2. 1 x 512
// ---------------------------------------------------------------------------
__global__ void final_kernel(const float* __restrict__ fc1_w,
                             const float* __restrict__ fc1_b,
                             const float* __restrict__ fc2_w,
                             const float* __restrict__ fc2_b,
                             float* __restrict__ out) {
    __shared__ float avg[FEAT];
    __shared__ float r0[16], r1[16];
    int tid = threadIdx.x;
    if (tid < GD) avg[tid] = g_gsum[tid] * (1.f / NW);
    else if (tid < FEAT) avg[tid] = g_hsum[tid - GD] * (1.f / NW);
    __syncthreads();

    float h = fc1_b[tid];
    const float* w = fc1_w + tid * FEAT;
#pragma unroll 4
    for (int k = 0; k < FEAT; k++) h = fmaf(w[k], avg[k], h);
    h = fmaxf(h, 0.f);

    float p0 = fc2_w[tid] * h;
    float p1 = fc2_w[HID + tid] * h;
#pragma unroll
    for (int off = 16; off; off >>= 1) {
        p0 += __shfl_down_sync(0xffffffffu, p0, off);
        p1 += __shfl_down_sync(0xffffffffu, p1, off);
    }
    int warp = tid >> 5, lane = tid & 31;
    if (lane == 0) { r0[warp] = p0; r1[warp] = p1; }
    __syncthreads();
    if (tid == 0) {
        float a = 0.f, b = 0.f;
#pragma unroll
        for (int i = 0; i < 16; i++) { a += r0[i]; b += r1[i]; }
        out[0] = a + fc2_b[0];
        out[1] = b + fc2_b[1];
    }
}

// ---------------------------------------------------------------------------
extern "C" void kernel_launch(void* const* d_in, const int* in_sizes, int n_in,
                              void* d_out, int out_size) {
    const int*   widx  = (const int*)d_in[0];
    const int*   cidx  = (const int*)d_in[1];
    const float* glove = (const float*)d_in[2];
    const float* cemb  = (const float*)d_in[3];
    const float* W_ih  = (const float*)d_in[4];
    const float* W_hh  = (const float*)d_in[5];
    const float* b_ih  = (const float*)d_in[6];
    const float* b_hh  = (const float*)d_in[7];
    const float* fc1_w = (const float*)d_in[8];
    const float* fc1_b = (const float*)d_in[9];
    const float* fc2_w = (const float*)d_in[10];
    const float* fc2_b = (const float*)d_in[11];
    float* out = (float*)d_out;

    cudaFuncSetAttribute(lstm_mma_kernel,
                         cudaFuncAttributeMaxDynamicSharedMemorySize, SM_TOTAL);

    prep_all<<<G4 + CV, 96>>>(W_hh, W_ih, b_ih, b_hh, cemb);
    lstm_mma_kernel<<<NBLK, THR, SM_TOTAL>>>(cidx, widx, glove);
    final_kernel<<<1, 512>>>(fc1_w, fc1_b, fc2_w, fc2_b, out);
}